// round 3
// baseline (speedup 1.0000x reference)
#include <cuda_runtime.h>

// Problem shape (fixed by the reference):
//   B=4, S=2048, D=1024
//   Q = queries @ Wq^T + bq            (3 projections, M=8192,N=1024,K=1024)
//   Sc = relu(Q @ K^T)   per batch     (M=2048,N=2048,K=1024, x4)
//   O  = Sc @ V          per batch     (M=2048,N=1024,K=2048, x4)

#define BATCH 4
#define SEQ   2048
#define DIM   1024

#define BM 128
#define BN 128
#define BK 16
#define TM 8
#define TN 8

// Device-global scratch (no allocations allowed).
__device__ float g_Q[(size_t)BATCH * SEQ * DIM];   // 33.5 MB
__device__ float g_K[(size_t)BATCH * SEQ * DIM];   // 33.5 MB
__device__ float g_V[(size_t)BATCH * SEQ * DIM];   // 33.5 MB
__device__ float g_S[(size_t)BATCH * SEQ * SEQ];   // 64 MB

// Generic fp32 SGEMM.
//  A: [M,K] row-major.
//  B_KMAJOR=true : B is [N,K] row-major  -> C = A * B^T   (NT)
//  B_KMAJOR=false: B is [K,N] row-major  -> C = A * B     (NN)
//  Optional bias[n] add and relu on the output.
//  Batched via blockIdx.z with element strides sA/sB/sC.
template <bool B_KMAJOR, bool RELU, bool BIAS>
__global__ __launch_bounds__(256)
void gemm_kernel(const float* __restrict__ A,
                 const float* __restrict__ B,
                 const float* __restrict__ bias,
                 float* __restrict__ C,
                 int M, int N, int K,
                 long long sA, long long sB, long long sC)
{
    __shared__ float As[BK][BM];
    __shared__ float Bs[BK][BN];

    A += (long long)blockIdx.z * sA;
    B += (long long)blockIdx.z * sB;
    C += (long long)blockIdx.z * sC;

    const int tid = threadIdx.x;
    const int tx = tid & 15;        // 0..15  -> N direction
    const int ty = tid >> 4;        // 0..15  -> M direction
    const int bm = blockIdx.y * BM;
    const int bn = blockIdx.x * BN;

    float acc[TM][TN];
#pragma unroll
    for (int i = 0; i < TM; i++)
#pragma unroll
        for (int j = 0; j < TN; j++) acc[i][j] = 0.0f;

    for (int kt = 0; kt < K; kt += BK) {
        // ---- load A tile [BM x BK], store transposed As[k][m] ----
#pragma unroll
        for (int p = 0; p < 2; p++) {
            int row = p * 64 + (tid >> 2);        // 0..127
            int kc  = (tid & 3) * 4;              // 0,4,8,12
            float4 v = *(const float4*)(A + (long long)(bm + row) * K + kt + kc);
            As[kc + 0][row] = v.x;
            As[kc + 1][row] = v.y;
            As[kc + 2][row] = v.z;
            As[kc + 3][row] = v.w;
        }
        // ---- load B tile ----
        if constexpr (B_KMAJOR) {
            // B[N,K] row-major: same pattern as A, store Bs[k][n]
#pragma unroll
            for (int p = 0; p < 2; p++) {
                int row = p * 64 + (tid >> 2);
                int kc  = (tid & 3) * 4;
                float4 v = *(const float4*)(B + (long long)(bn + row) * K + kt + kc);
                Bs[kc + 0][row] = v.x;
                Bs[kc + 1][row] = v.y;
                Bs[kc + 2][row] = v.z;
                Bs[kc + 3][row] = v.w;
            }
        } else {
            // B[K,N] row-major: rows are n-contiguous, direct vector store
#pragma unroll
            for (int p = 0; p < 2; p++) {
                int kr = p * 8 + (tid >> 5);      // 0..15
                int nc = (tid & 31) * 4;          // 0..124
                *(float4*)&Bs[kr][nc] =
                    *(const float4*)(B + (long long)(kt + kr) * N + bn + nc);
            }
        }
        __syncthreads();

        // ---- compute ----
#pragma unroll
        for (int k = 0; k < BK; k++) {
            float a[TM], b[TN];
            *(float4*)&a[0] = *(const float4*)&As[k][ty * TM];
            *(float4*)&a[4] = *(const float4*)&As[k][ty * TM + 4];
            *(float4*)&b[0] = *(const float4*)&Bs[k][tx * TN];
            *(float4*)&b[4] = *(const float4*)&Bs[k][tx * TN + 4];
#pragma unroll
            for (int i = 0; i < TM; i++)
#pragma unroll
                for (int j = 0; j < TN; j++)
                    acc[i][j] = fmaf(a[i], b[j], acc[i][j]);
        }
        __syncthreads();
    }

    // ---- epilogue: bias / relu / store ----
#pragma unroll
    for (int i = 0; i < TM; i++) {
        long long row = bm + ty * TM + i;
#pragma unroll
        for (int j4 = 0; j4 < TN; j4 += 4) {
            int n = bn + tx * TN + j4;
            float4 v;
            v.x = acc[i][j4 + 0];
            v.y = acc[i][j4 + 1];
            v.z = acc[i][j4 + 2];
            v.w = acc[i][j4 + 3];
            if constexpr (BIAS) {
                v.x += bias[n + 0];
                v.y += bias[n + 1];
                v.z += bias[n + 2];
                v.w += bias[n + 3];
            }
            if constexpr (RELU) {
                v.x = fmaxf(v.x, 0.0f);
                v.y = fmaxf(v.y, 0.0f);
                v.z = fmaxf(v.z, 0.0f);
                v.w = fmaxf(v.w, 0.0f);
            }
            *(float4*)(C + row * N + n) = v;
        }
    }
}

extern "C" void kernel_launch(void* const* d_in, const int* in_sizes, int n_in,
                              void* d_out, int out_size)
{
    const float* queries = (const float*)d_in[0];
    const float* keys    = (const float*)d_in[1];
    const float* values  = (const float*)d_in[2];
    const float* Wq      = (const float*)d_in[3];
    const float* bq      = (const float*)d_in[4];
    const float* Wk      = (const float*)d_in[5];
    const float* bk      = (const float*)d_in[6];
    const float* Wv      = (const float*)d_in[7];
    const float* bv      = (const float*)d_in[8];
    float* out = (float*)d_out;

    float *Qp, *Kp, *Vp, *Sp;
    cudaGetSymbolAddress((void**)&Qp, g_Q);
    cudaGetSymbolAddress((void**)&Kp, g_K);
    cudaGetSymbolAddress((void**)&Vp, g_V);
    cudaGetSymbolAddress((void**)&Sp, g_S);

    const int M_proj = BATCH * SEQ;   // 8192
    dim3 blk(256);

    // 1) Projections: X[8192,1024] @ W^T[1024,1024] + b  (NT, bias)
    dim3 gproj(DIM / BN, M_proj / BM, 1);
    gemm_kernel<true, false, true><<<gproj, blk>>>(
        queries, Wq, bq, Qp, M_proj, DIM, DIM, 0, 0, 0);
    gemm_kernel<true, false, true><<<gproj, blk>>>(
        keys, Wk, bk, Kp, M_proj, DIM, DIM, 0, 0, 0);
    gemm_kernel<true, false, true><<<gproj, blk>>>(
        values, Wv, bv, Vp, M_proj, DIM, DIM, 0, 0, 0);

    // 2) Scores: relu(Q @ K^T) per batch  (NT, relu), batched over z
    dim3 gs(SEQ / BN, SEQ / BM, BATCH);
    gemm_kernel<true, true, false><<<gs, blk>>>(
        Qp, Kp, nullptr, Sp, SEQ, SEQ, DIM,
        (long long)SEQ * DIM, (long long)SEQ * DIM, (long long)SEQ * SEQ);

    // 3) Output: Sc @ V per batch  (NN), batched over z
    dim3 go(DIM / BN, SEQ / BM, BATCH);
    gemm_kernel<false, false, false><<<go, blk>>>(
        Sp, Vp, nullptr, out, SEQ, DIM, SEQ,
        (long long)SEQ * SEQ, (long long)SEQ * DIM, (long long)SEQ * DIM);

    (void)in_sizes; (void)n_in; (void)out_size;
}

// round 6
// speedup vs baseline: 1.7223x; 1.7223x over previous
#include <cuda_runtime.h>
#include <cuda_bf16.h>
#include <cstdint>

// ---------------------------------------------------------------------------
// Problem: B=4, S=2048, D=1024
//   Q = q_in @ Wq^T + bq ; K = k_in @ Wk^T + bk ; V = v_in @ Wv^T + bv
//   Sc = relu(Q @ K^T) per batch ;  O = Sc @ V per batch
// All GEMMs on mma.sync.m16n8k16 bf16 tensor cores (base sm_103 target — the
// harness PTX target rejects tcgen05) with 2-term bf16 operand splitting
// (hi*hi + hi*lo + lo*hi) for fp32-class accuracy.
// ---------------------------------------------------------------------------

#define BATCH 4
#define SEQ   2048
#define DIM   1024

#define BM 128
#define BN 256
#define KC 64                       // bf16 per K chunk = 128 bytes/row

#define TILE_A_BYTES (BM * 128)     // 16 KB per split
#define TILE_B_BYTES (BN * 128)     // 32 KB per split
#define OFF_AH 0
#define OFF_AL (TILE_A_BYTES)
#define OFF_BH (2 * TILE_A_BYTES)
#define OFF_BL (2 * TILE_A_BYTES + TILE_B_BYTES)
#define STAGE_BYTES (2 * TILE_A_BYTES + 2 * TILE_B_BYTES)   // 96 KB
#define SMEM_TOTAL (2 * STAGE_BYTES)                        // 192 KB

#define EP_LD 260                   // epilogue smem row stride (u32)

// ---------------- device-global scratch (no allocations allowed) -----------
__device__ __nv_bfloat16 g_qi_h[(size_t)BATCH * SEQ * DIM];
__device__ __nv_bfloat16 g_qi_l[(size_t)BATCH * SEQ * DIM];
__device__ __nv_bfloat16 g_ki_h[(size_t)BATCH * SEQ * DIM];
__device__ __nv_bfloat16 g_ki_l[(size_t)BATCH * SEQ * DIM];
__device__ __nv_bfloat16 g_vi_h[(size_t)BATCH * SEQ * DIM];
__device__ __nv_bfloat16 g_vi_l[(size_t)BATCH * SEQ * DIM];
__device__ __nv_bfloat16 g_wq_h[(size_t)DIM * DIM];
__device__ __nv_bfloat16 g_wq_l[(size_t)DIM * DIM];
__device__ __nv_bfloat16 g_wk_h[(size_t)DIM * DIM];
__device__ __nv_bfloat16 g_wk_l[(size_t)DIM * DIM];
__device__ __nv_bfloat16 g_wv_h[(size_t)DIM * DIM];
__device__ __nv_bfloat16 g_wv_l[(size_t)DIM * DIM];
__device__ __nv_bfloat16 g_Q_h[(size_t)BATCH * SEQ * DIM];
__device__ __nv_bfloat16 g_Q_l[(size_t)BATCH * SEQ * DIM];
__device__ __nv_bfloat16 g_K_h[(size_t)BATCH * SEQ * DIM];
__device__ __nv_bfloat16 g_K_l[(size_t)BATCH * SEQ * DIM];
__device__ __nv_bfloat16 g_Vt_h[(size_t)BATCH * DIM * SEQ];   // [b][d][s]
__device__ __nv_bfloat16 g_Vt_l[(size_t)BATCH * DIM * SEQ];
__device__ __nv_bfloat16 g_S_h[(size_t)BATCH * SEQ * SEQ];
__device__ __nv_bfloat16 g_S_l[(size_t)BATCH * SEQ * SEQ];

// ----------------------------- asm helpers --------------------------------
__device__ __forceinline__ uint32_t smem_u32(const void* p) {
    uint32_t a;
    asm("{ .reg .u64 t; cvta.to.shared.u64 t, %1; cvt.u32.u64 %0, t; }"
        : "=r"(a) : "l"(p));
    return a;
}

__device__ __forceinline__ void cp16(uint32_t dst, const void* src) {
    asm volatile("cp.async.cg.shared.global [%0], [%1], 16;" :: "r"(dst), "l"(src));
}

#define LDSM4(r, addr) \
    asm volatile("ldmatrix.sync.aligned.m8n8.x4.shared.b16 {%0,%1,%2,%3}, [%4];" \
        : "=r"((r)[0]), "=r"((r)[1]), "=r"((r)[2]), "=r"((r)[3]) : "r"(addr))

#define MMA(c, a, b0, b1) \
    asm volatile("mma.sync.aligned.m16n8k16.row.col.f32.bf16.bf16.f32 " \
        "{%0,%1,%2,%3}, {%4,%5,%6,%7}, {%8,%9}, {%0,%1,%2,%3};" \
        : "+f"((c)[0]), "+f"((c)[1]), "+f"((c)[2]), "+f"((c)[3]) \
        : "r"((a)[0]), "r"((a)[1]), "r"((a)[2]), "r"((a)[3]), "r"(b0), "r"(b1))

// Load one stage: A(hi,lo) 128x64 bf16 + B(hi,lo) 256x64 bf16 (96 KB).
// Smem layout per split: row*128B, 16B chunk c16 swizzled by (c16 ^ (row&7)).
__device__ __forceinline__ void load_stage(
    uint32_t sb,
    const __nv_bfloat16* __restrict__ Ah, const __nv_bfloat16* __restrict__ Al,
    const __nv_bfloat16* __restrict__ Bh, const __nv_bfloat16* __restrict__ Bl,
    int bm, int bn, int K, int kt, int tid)
{
#pragma unroll
    for (int it = 0; it < 24; it++) {
        int lin = it * 256 + tid;
        const __nv_bfloat16* gp;
        uint32_t toff;
        int c;
        if (it < 4)       { c = lin;        gp = Ah + (long long)(bm + (c >> 3)) * K; toff = OFF_AH; }
        else if (it < 8)  { c = lin - 1024; gp = Al + (long long)(bm + (c >> 3)) * K; toff = OFF_AL; }
        else if (it < 16) { c = lin - 2048; gp = Bh + (long long)(bn + (c >> 3)) * K; toff = OFF_BH; }
        else              { c = lin - 4096; gp = Bl + (long long)(bn + (c >> 3)) * K; toff = OFF_BL; }
        int row = c >> 3;
        int c16 = c & 7;
        uint32_t dst = sb + toff + (uint32_t)row * 128u +
                       (uint32_t)((c16 ^ (row & 7)) << 4);
        cp16(dst, gp + kt + c16 * 8);
    }
}

// ---------------------------------------------------------------------------
// Tensor-core GEMM: C[M,N] = A[M,K] @ B[N,K]^T   (both K-major, bf16 hi/lo)
// MODE 0: fp32 out ; MODE 1: split bf16 hi/lo out (row-major) ;
// MODE 2: split bf16 out, transposed per-batch into [b][n][m%SEQ] (Vt).
// ---------------------------------------------------------------------------
template <int MODE, bool RELU, bool BIAS>
__global__ __launch_bounds__(256, 1)
void tc_gemm(const __nv_bfloat16* __restrict__ Ah, const __nv_bfloat16* __restrict__ Al,
             const __nv_bfloat16* __restrict__ Bh, const __nv_bfloat16* __restrict__ Bl,
             const float* __restrict__ bias,
             float* __restrict__ Cf,
             __nv_bfloat16* __restrict__ Ch, __nv_bfloat16* __restrict__ Cl,
             int K, int ldc, long long sA, long long sB, long long sC)
{
    extern __shared__ char smem[];
    const uint32_t su = smem_u32(smem);
    const int tid  = threadIdx.x;
    const int lane = tid & 31;
    const int wid  = tid >> 5;
    const int warp_m = (wid & 1) * 64;
    const int warp_n = (wid >> 1) * 64;
    const int bm = blockIdx.y * BM;
    const int bn = blockIdx.x * BN;
    const int z  = blockIdx.z;
    Ah += (long long)z * sA;  Al += (long long)z * sA;
    Bh += (long long)z * sB;  Bl += (long long)z * sB;

    float acc[4][8][4];
#pragma unroll
    for (int i = 0; i < 4; i++)
#pragma unroll
        for (int j = 0; j < 8; j++)
#pragma unroll
            for (int k = 0; k < 4; k++) acc[i][j][k] = 0.0f;

    const int nc = K / KC;

    load_stage(su, Ah, Al, Bh, Bl, bm, bn, K, 0, tid);
    asm volatile("cp.async.commit_group;" ::: "memory");
    load_stage(su + STAGE_BYTES, Ah, Al, Bh, Bl, bm, bn, K, KC, tid);
    asm volatile("cp.async.commit_group;" ::: "memory");

    // per-lane ldmatrix addressing components
    const int arow  = ((lane >> 3) & 1) * 8 + (lane & 7);  // row within 16-row frag
    const int chalf = lane >> 4;                           // k-half (16B chunk)
    const int swz   = lane & 7;

    for (int i = 0; i < nc; i++) {
        if (i + 1 < nc) asm volatile("cp.async.wait_group 1;" ::: "memory");
        else            asm volatile("cp.async.wait_group 0;" ::: "memory");
        __syncthreads();

        const uint32_t sb = su + (uint32_t)(i & 1) * STAGE_BYTES;
        const uint32_t aRow = sb + (uint32_t)(warp_m + arow) * 128u;
        const uint32_t bRow = sb + (uint32_t)(warp_n + arow) * 128u;

#pragma unroll
        for (int ks = 0; ks < 4; ks++) {
            const uint32_t cb = (uint32_t)(((ks * 2 + chalf) ^ swz) << 4);
            uint32_t fah[4][4], fal[4][4], fbh[4][4], fbl[4][4];
#pragma unroll
            for (int im = 0; im < 4; im++) {
                LDSM4(fah[im], aRow + OFF_AH + im * 2048u + cb);
                LDSM4(fal[im], aRow + OFF_AL + im * 2048u + cb);
            }
#pragma unroll
            for (int jn = 0; jn < 4; jn++) {
                LDSM4(fbh[jn], bRow + OFF_BH + jn * 2048u + cb);
                LDSM4(fbl[jn], bRow + OFF_BL + jn * 2048u + cb);
            }
#pragma unroll
            for (int im = 0; im < 4; im++) {
#pragma unroll
                for (int jn = 0; jn < 4; jn++) {
                    MMA(acc[im][2 * jn],     fah[im], fbh[jn][0], fbh[jn][2]);
                    MMA(acc[im][2 * jn + 1], fah[im], fbh[jn][1], fbh[jn][3]);
                    MMA(acc[im][2 * jn],     fah[im], fbl[jn][0], fbl[jn][2]);
                    MMA(acc[im][2 * jn + 1], fah[im], fbl[jn][1], fbl[jn][3]);
                    MMA(acc[im][2 * jn],     fal[im], fbh[jn][0], fbh[jn][2]);
                    MMA(acc[im][2 * jn + 1], fal[im], fbh[jn][1], fbh[jn][3]);
                }
            }
        }
        __syncthreads();
        if (i + 2 < nc) {
            load_stage(su + (uint32_t)(i & 1) * STAGE_BYTES,
                       Ah, Al, Bh, Bl, bm, bn, K, (i + 2) * KC, tid);
            asm volatile("cp.async.commit_group;" ::: "memory");
        }
    }

    // ---- epilogue: regs -> smem stage (bias/relu/convert) -> coalesced gmem ----
    uint32_t* stage = (uint32_t*)smem;
#pragma unroll
    for (int im = 0; im < 4; im++) {
#pragma unroll
        for (int j8 = 0; j8 < 8; j8++) {
            int r0 = warp_m + im * 16 + (lane >> 2);
            int c0 = warp_n + j8 * 8 + (lane & 3) * 2;
#pragma unroll
            for (int half = 0; half < 2; half++) {
                int r = r0 + half * 8;
#pragma unroll
                for (int cc = 0; cc < 2; cc++) {
                    float v = acc[im][j8][half * 2 + cc];
                    int c = c0 + cc;
                    if (BIAS) v += bias[bn + c];
                    if (RELU) v = fmaxf(v, 0.0f);
                    uint32_t w;
                    if (MODE == 0) {
                        w = __float_as_uint(v);
                    } else {
                        __nv_bfloat16 h = __float2bfloat16_rn(v);
                        float hf = __bfloat162float(h);
                        __nv_bfloat16 l = __float2bfloat16_rn(v - hf);
                        w = (uint32_t)__bfloat16_as_ushort(h) |
                            ((uint32_t)__bfloat16_as_ushort(l) << 16);
                    }
                    stage[r * EP_LD + c] = w;
                }
            }
        }
    }
    __syncthreads();

    if (MODE == 0) {
        float* Cp = Cf + (long long)z * sC;
#pragma unroll 4
        for (int k2 = 0; k2 < 128; k2++) {
            int idx = tid + k2 * 256;
            int r = idx >> 8, c = idx & 255;
            Cp[(long long)(bm + r) * ldc + bn + c] =
                __uint_as_float(stage[r * EP_LD + c]);
        }
    } else if (MODE == 1) {
        __nv_bfloat16* ChP = Ch + (long long)z * sC;
        __nv_bfloat16* ClP = Cl + (long long)z * sC;
#pragma unroll 4
        for (int k2 = 0; k2 < 64; k2++) {
            int p = tid + k2 * 256;
            int r = p >> 7, cp2 = (p & 127) * 2;
            uint32_t w0 = stage[r * EP_LD + cp2];
            uint32_t w1 = stage[r * EP_LD + cp2 + 1];
            uint32_t hw = (w0 & 0xFFFFu) | (w1 << 16);
            uint32_t lw = (w0 >> 16) | (w1 & 0xFFFF0000u);
            long long o = (long long)(bm + r) * ldc + bn + cp2;
            *(uint32_t*)(ChP + o) = hw;
            *(uint32_t*)(ClP + o) = lw;
        }
    } else {
        // Transposed split store: Vt[b][d][s], b = bm/SEQ, d = bn+c, s = bm%SEQ+r
        long long ob = (long long)(bm >> 11) * ((long long)DIM * SEQ);
        int sbase = bm & (SEQ - 1);
#pragma unroll 1
        for (int cc = 0; cc < 32; cc++) {
            int c = (tid >> 5) + cc * 8;
#pragma unroll
            for (int rr = 0; rr < 4; rr++) {
                int r = (tid & 31) + rr * 32;
                uint32_t w = stage[r * EP_LD + c];
                long long o = ob + (long long)(bn + c) * SEQ + sbase + r;
                Ch[o] = __ushort_as_bfloat16((unsigned short)(w & 0xFFFF));
                Cl[o] = __ushort_as_bfloat16((unsigned short)(w >> 16));
            }
        }
    }
}

// ------------------- fp32 -> bf16 hi/lo split (prep) -----------------------
__global__ __launch_bounds__(256)
void split_kernel(const float* __restrict__ x,
                  __nv_bfloat16* __restrict__ h, __nv_bfloat16* __restrict__ l,
                  int n)
{
    int i = (blockIdx.x * 256 + threadIdx.x) * 4;
    if (i >= n) return;
    float4 v = *(const float4*)(x + i);
    float vv[4] = {v.x, v.y, v.z, v.w};
    unsigned short hs[4], ls[4];
#pragma unroll
    for (int j = 0; j < 4; j++) {
        __nv_bfloat16 hb = __float2bfloat16_rn(vv[j]);
        float hf = __bfloat162float(hb);
        __nv_bfloat16 lb = __float2bfloat16_rn(vv[j] - hf);
        hs[j] = __bfloat16_as_ushort(hb);
        ls[j] = __bfloat16_as_ushort(lb);
    }
    uint2 hw = make_uint2((uint32_t)hs[0] | ((uint32_t)hs[1] << 16),
                          (uint32_t)hs[2] | ((uint32_t)hs[3] << 16));
    uint2 lw = make_uint2((uint32_t)ls[0] | ((uint32_t)ls[1] << 16),
                          (uint32_t)ls[2] | ((uint32_t)ls[3] << 16));
    *(uint2*)(h + i) = hw;
    *(uint2*)(l + i) = lw;
}

// ---------------------------------------------------------------------------
extern "C" void kernel_launch(void* const* d_in, const int* in_sizes, int n_in,
                              void* d_out, int out_size)
{
    const float* queries = (const float*)d_in[0];
    const float* keys    = (const float*)d_in[1];
    const float* values  = (const float*)d_in[2];
    const float* Wq      = (const float*)d_in[3];
    const float* bq      = (const float*)d_in[4];
    const float* Wk      = (const float*)d_in[5];
    const float* bk      = (const float*)d_in[6];
    const float* Wv      = (const float*)d_in[7];
    const float* bv      = (const float*)d_in[8];
    float* out = (float*)d_out;

    __nv_bfloat16 *qih, *qil, *kih, *kil, *vih, *vil;
    __nv_bfloat16 *wqh, *wql, *wkh, *wkl, *wvh, *wvl;
    __nv_bfloat16 *Qh, *Ql, *Kh, *Kl, *Vth, *Vtl, *Sh, *Sl;
    cudaGetSymbolAddress((void**)&qih, g_qi_h); cudaGetSymbolAddress((void**)&qil, g_qi_l);
    cudaGetSymbolAddress((void**)&kih, g_ki_h); cudaGetSymbolAddress((void**)&kil, g_ki_l);
    cudaGetSymbolAddress((void**)&vih, g_vi_h); cudaGetSymbolAddress((void**)&vil, g_vi_l);
    cudaGetSymbolAddress((void**)&wqh, g_wq_h); cudaGetSymbolAddress((void**)&wql, g_wq_l);
    cudaGetSymbolAddress((void**)&wkh, g_wk_h); cudaGetSymbolAddress((void**)&wkl, g_wk_l);
    cudaGetSymbolAddress((void**)&wvh, g_wv_h); cudaGetSymbolAddress((void**)&wvl, g_wv_l);
    cudaGetSymbolAddress((void**)&Qh,  g_Q_h);  cudaGetSymbolAddress((void**)&Ql,  g_Q_l);
    cudaGetSymbolAddress((void**)&Kh,  g_K_h);  cudaGetSymbolAddress((void**)&Kl,  g_K_l);
    cudaGetSymbolAddress((void**)&Vth, g_Vt_h); cudaGetSymbolAddress((void**)&Vtl, g_Vt_l);
    cudaGetSymbolAddress((void**)&Sh,  g_S_h);  cudaGetSymbolAddress((void**)&Sl,  g_S_l);

    cudaFuncSetAttribute(tc_gemm<1, false, true>,
                         cudaFuncAttributeMaxDynamicSharedMemorySize, SMEM_TOTAL);
    cudaFuncSetAttribute(tc_gemm<2, false, true>,
                         cudaFuncAttributeMaxDynamicSharedMemorySize, SMEM_TOTAL);
    cudaFuncSetAttribute(tc_gemm<1, true, false>,
                         cudaFuncAttributeMaxDynamicSharedMemorySize, SMEM_TOTAL);
    cudaFuncSetAttribute(tc_gemm<0, false, false>,
                         cudaFuncAttributeMaxDynamicSharedMemorySize, SMEM_TOTAL);

    const int nIn = BATCH * SEQ * DIM;   // 8388608
    const int nW  = DIM * DIM;           // 1048576

    // 0) split inputs + weights into bf16 hi/lo
    split_kernel<<<nIn / 1024, 256>>>(queries, qih, qil, nIn);
    split_kernel<<<nIn / 1024, 256>>>(keys,    kih, kil, nIn);
    split_kernel<<<nIn / 1024, 256>>>(values,  vih, vil, nIn);
    split_kernel<<<nW  / 1024, 256>>>(Wq, wqh, wql, nW);
    split_kernel<<<nW  / 1024, 256>>>(Wk, wkh, wkl, nW);
    split_kernel<<<nW  / 1024, 256>>>(Wv, wvh, wvl, nW);

    const int Mproj = BATCH * SEQ;       // 8192
    dim3 blk(256);

    // 1) projections (M=8192, N=1024, K=1024)
    dim3 gp(DIM / BN, Mproj / BM, 1);
    tc_gemm<1, false, true><<<gp, blk, SMEM_TOTAL>>>(
        qih, qil, wqh, wql, bq, nullptr, Qh, Ql, DIM, DIM, 0, 0, 0);
    tc_gemm<1, false, true><<<gp, blk, SMEM_TOTAL>>>(
        kih, kil, wkh, wkl, bk, nullptr, Kh, Kl, DIM, DIM, 0, 0, 0);
    tc_gemm<2, false, true><<<gp, blk, SMEM_TOTAL>>>(
        vih, vil, wvh, wvl, bv, nullptr, Vth, Vtl, DIM, 0, 0, 0, 0);

    // 2) scores: relu(Q @ K^T) per batch (M=2048, N=2048, K=1024)
    dim3 gs(SEQ / BN, SEQ / BM, BATCH);
    tc_gemm<1, true, false><<<gs, blk, SMEM_TOTAL>>>(
        Qh, Ql, Kh, Kl, nullptr, nullptr, Sh, Sl, DIM, SEQ,
        (long long)SEQ * DIM, (long long)SEQ * DIM, (long long)SEQ * SEQ);

    // 3) output: Sc @ Vt^T per batch (M=2048, N=1024, K=2048)
    dim3 go(DIM / BN, SEQ / BM, BATCH);
    tc_gemm<0, false, false><<<go, blk, SMEM_TOTAL>>>(
        Sh, Sl, Vth, Vtl, nullptr, out, nullptr, nullptr, SEQ, DIM,
        (long long)SEQ * SEQ, (long long)DIM * SEQ, (long long)SEQ * DIM);

    (void)in_sizes; (void)n_in; (void)out_size;
}

// round 8
// speedup vs baseline: 2.6460x; 1.5363x over previous
#include <cuda_runtime.h>
#include <cuda_bf16.h>
#include <cstdint>

// ---------------------------------------------------------------------------
// Problem: B=4, S=2048, D=1024
//   Q = q_in @ Wq^T + bq ; K = k_in @ Wk^T + bk ; V = v_in @ Wv^T + bv
//   Sc = relu(Q @ K^T) per batch ;  O = Sc @ V per batch
// All GEMMs on mma.sync.m16n8k16 bf16 tensor cores with 2-term bf16 operand
// splitting (hi*hi + hi*lo + lo*hi) for fp32-class accuracy.
// ---------------------------------------------------------------------------

#define BATCH 4
#define SEQ   2048
#define DIM   1024

#define BM 128
#define BN 256
#define KC 64                       // bf16 per K chunk = 128 bytes/row

#define TILE_A_BYTES (BM * 128)     // 16 KB per split
#define TILE_B_BYTES (BN * 128)     // 32 KB per split
#define OFF_AH 0
#define OFF_AL (TILE_A_BYTES)
#define OFF_BH (2 * TILE_A_BYTES)
#define OFF_BL (2 * TILE_A_BYTES + TILE_B_BYTES)
#define STAGE_BYTES (2 * TILE_A_BYTES + 2 * TILE_B_BYTES)   // 96 KB
#define SMEM_TOTAL (2 * STAGE_BYTES)                        // 192 KB

#define EP_LD 260                   // epilogue smem row stride (u32)

// ---------------- device-global scratch (no allocations allowed) -----------
__device__ __nv_bfloat16 g_qi_h[(size_t)BATCH * SEQ * DIM];
__device__ __nv_bfloat16 g_qi_l[(size_t)BATCH * SEQ * DIM];
__device__ __nv_bfloat16 g_ki_h[(size_t)BATCH * SEQ * DIM];
__device__ __nv_bfloat16 g_ki_l[(size_t)BATCH * SEQ * DIM];
__device__ __nv_bfloat16 g_vi_h[(size_t)BATCH * SEQ * DIM];
__device__ __nv_bfloat16 g_vi_l[(size_t)BATCH * SEQ * DIM];
__device__ __nv_bfloat16 g_wq_h[(size_t)DIM * DIM];
__device__ __nv_bfloat16 g_wq_l[(size_t)DIM * DIM];
__device__ __nv_bfloat16 g_wk_h[(size_t)DIM * DIM];
__device__ __nv_bfloat16 g_wk_l[(size_t)DIM * DIM];
__device__ __nv_bfloat16 g_wv_h[(size_t)DIM * DIM];
__device__ __nv_bfloat16 g_wv_l[(size_t)DIM * DIM];
__device__ __nv_bfloat16 g_Q_h[(size_t)BATCH * SEQ * DIM];
__device__ __nv_bfloat16 g_Q_l[(size_t)BATCH * SEQ * DIM];
__device__ __nv_bfloat16 g_K_h[(size_t)BATCH * SEQ * DIM];
__device__ __nv_bfloat16 g_K_l[(size_t)BATCH * SEQ * DIM];
__device__ __nv_bfloat16 g_Vt_h[(size_t)BATCH * DIM * SEQ];   // [b][d][s]
__device__ __nv_bfloat16 g_Vt_l[(size_t)BATCH * DIM * SEQ];
__device__ __nv_bfloat16 g_S_h[(size_t)BATCH * SEQ * SEQ];
__device__ __nv_bfloat16 g_S_l[(size_t)BATCH * SEQ * SEQ];

// ----------------------------- asm helpers --------------------------------
__device__ __forceinline__ uint32_t smem_u32(const void* p) {
    uint32_t a;
    asm("{ .reg .u64 t; cvta.to.shared.u64 t, %1; cvt.u32.u64 %0, t; }"
        : "=r"(a) : "l"(p));
    return a;
}

__device__ __forceinline__ void cp16(uint32_t dst, const void* src) {
    asm volatile("cp.async.cg.shared.global [%0], [%1], 16;" :: "r"(dst), "l"(src));
}

#define LDSM4(r, addr) \
    asm volatile("ldmatrix.sync.aligned.m8n8.x4.shared.b16 {%0,%1,%2,%3}, [%4];" \
        : "=r"((r)[0]), "=r"((r)[1]), "=r"((r)[2]), "=r"((r)[3]) : "r"(addr))

#define MMA(c, a, b0, b1) \
    asm volatile("mma.sync.aligned.m16n8k16.row.col.f32.bf16.bf16.f32 " \
        "{%0,%1,%2,%3}, {%4,%5,%6,%7}, {%8,%9}, {%0,%1,%2,%3};" \
        : "+f"((c)[0]), "+f"((c)[1]), "+f"((c)[2]), "+f"((c)[3]) \
        : "r"((a)[0]), "r"((a)[1]), "r"((a)[2]), "r"((a)[3]), "r"(b0), "r"(b1))

// Load one stage: A(hi,lo) 128x64 bf16 + B(hi,lo) 256x64 bf16 (96 KB).
// Smem layout per split: row*128B, 16B chunk c16 swizzled by (c16 ^ (row&7)).
__device__ __forceinline__ void load_stage(
    uint32_t sb,
    const __nv_bfloat16* __restrict__ Ah, const __nv_bfloat16* __restrict__ Al,
    const __nv_bfloat16* __restrict__ Bh, const __nv_bfloat16* __restrict__ Bl,
    int bm, int bn, int K, int kt, int tid)
{
#pragma unroll
    for (int it = 0; it < 24; it++) {
        int lin = it * 256 + tid;
        const __nv_bfloat16* gp;
        uint32_t toff;
        int c;
        if (it < 4)       { c = lin;        gp = Ah + (long long)(bm + (c >> 3)) * K; toff = OFF_AH; }
        else if (it < 8)  { c = lin - 1024; gp = Al + (long long)(bm + (c >> 3)) * K; toff = OFF_AL; }
        else if (it < 16) { c = lin - 2048; gp = Bh + (long long)(bn + (c >> 3)) * K; toff = OFF_BH; }
        else              { c = lin - 4096; gp = Bl + (long long)(bn + (c >> 3)) * K; toff = OFF_BL; }
        int row = c >> 3;
        int c16 = c & 7;
        uint32_t dst = sb + toff + (uint32_t)row * 128u +
                       (uint32_t)((c16 ^ (row & 7)) << 4);
        cp16(dst, gp + kt + c16 * 8);
    }
}

// ---------------------------------------------------------------------------
// Tensor-core GEMM: C[M,N] = A[M,K] @ B[N,K]^T   (both K-major, bf16 hi/lo)
// MODE 0: fp32 out ; MODE 1: split bf16 hi/lo out (row-major) ;
// MODE 2: split bf16 out, transposed per-batch into [b][n][m%SEQ] (Vt).
// ---------------------------------------------------------------------------
template <int MODE, bool RELU, bool BIAS>
__global__ __launch_bounds__(256, 1)
void tc_gemm(const __nv_bfloat16* __restrict__ Ah, const __nv_bfloat16* __restrict__ Al,
             const __nv_bfloat16* __restrict__ Bh, const __nv_bfloat16* __restrict__ Bl,
             const float* __restrict__ bias,
             float* __restrict__ Cf,
             __nv_bfloat16* __restrict__ Ch, __nv_bfloat16* __restrict__ Cl,
             int K, int ldc, long long sA, long long sB, long long sC)
{
    extern __shared__ char smem[];
    const uint32_t su = smem_u32(smem);
    const int tid  = threadIdx.x;
    const int lane = tid & 31;
    const int wid  = tid >> 5;
    const int warp_m = (wid & 1) * 64;
    const int warp_n = (wid >> 1) * 64;
    const int bm = blockIdx.y * BM;
    const int bn = blockIdx.x * BN;
    const int z  = blockIdx.z;
    Ah += (long long)z * sA;  Al += (long long)z * sA;
    Bh += (long long)z * sB;  Bl += (long long)z * sB;

    float acc[4][8][4];
#pragma unroll
    for (int i = 0; i < 4; i++)
#pragma unroll
        for (int j = 0; j < 8; j++)
#pragma unroll
            for (int k = 0; k < 4; k++) acc[i][j][k] = 0.0f;

    const int nc = K / KC;

    load_stage(su, Ah, Al, Bh, Bl, bm, bn, K, 0, tid);
    asm volatile("cp.async.commit_group;" ::: "memory");
    load_stage(su + STAGE_BYTES, Ah, Al, Bh, Bl, bm, bn, K, KC, tid);
    asm volatile("cp.async.commit_group;" ::: "memory");

    // per-lane ldmatrix addressing components
    const int arow  = ((lane >> 3) & 1) * 8 + (lane & 7);  // row within 16-row frag
    const int chalf = lane >> 4;                           // k-half (16B chunk)
    const int swz   = lane & 7;

    for (int i = 0; i < nc; i++) {
        if (i + 1 < nc) asm volatile("cp.async.wait_group 1;" ::: "memory");
        else            asm volatile("cp.async.wait_group 0;" ::: "memory");
        __syncthreads();

        const uint32_t sb = su + (uint32_t)(i & 1) * STAGE_BYTES;
        const uint32_t aRow = sb + (uint32_t)(warp_m + arow) * 128u;
        const uint32_t bRow = sb + (uint32_t)(warp_n + arow) * 128u;

#pragma unroll
        for (int ks = 0; ks < 4; ks++) {
            const uint32_t cb = (uint32_t)(((ks * 2 + chalf) ^ swz) << 4);
            // Hoist only B fragments (32 regs); stream A fragments per im.
            uint32_t fbh[4][4], fbl[4][4];
#pragma unroll
            for (int jn = 0; jn < 4; jn++) {
                LDSM4(fbh[jn], bRow + OFF_BH + jn * 2048u + cb);
                LDSM4(fbl[jn], bRow + OFF_BL + jn * 2048u + cb);
            }
#pragma unroll
            for (int im = 0; im < 4; im++) {
                uint32_t fah[4], fal[4];
                LDSM4(fah, aRow + OFF_AH + im * 2048u + cb);
                LDSM4(fal, aRow + OFF_AL + im * 2048u + cb);
                // Pass 1: hi*hi  (full row sweep -> dependency distance 8)
#pragma unroll
                for (int jn = 0; jn < 4; jn++) {
                    MMA(acc[im][2 * jn],     fah, fbh[jn][0], fbh[jn][2]);
                    MMA(acc[im][2 * jn + 1], fah, fbh[jn][1], fbh[jn][3]);
                }
                // Pass 2: hi*lo
#pragma unroll
                for (int jn = 0; jn < 4; jn++) {
                    MMA(acc[im][2 * jn],     fah, fbl[jn][0], fbl[jn][2]);
                    MMA(acc[im][2 * jn + 1], fah, fbl[jn][1], fbl[jn][3]);
                }
                // Pass 3: lo*hi
#pragma unroll
                for (int jn = 0; jn < 4; jn++) {
                    MMA(acc[im][2 * jn],     fal, fbh[jn][0], fbh[jn][2]);
                    MMA(acc[im][2 * jn + 1], fal, fbh[jn][1], fbh[jn][3]);
                }
            }
        }
        __syncthreads();
        if (i + 2 < nc) {
            load_stage(su + (uint32_t)(i & 1) * STAGE_BYTES,
                       Ah, Al, Bh, Bl, bm, bn, K, (i + 2) * KC, tid);
            asm volatile("cp.async.commit_group;" ::: "memory");
        }
    }

    // ---- epilogue: regs -> smem stage (bias/relu/convert) -> coalesced gmem ----
    uint32_t* stage = (uint32_t*)smem;
#pragma unroll
    for (int im = 0; im < 4; im++) {
#pragma unroll
        for (int j8 = 0; j8 < 8; j8++) {
            int r0 = warp_m + im * 16 + (lane >> 2);
            int c0 = warp_n + j8 * 8 + (lane & 3) * 2;
#pragma unroll
            for (int half = 0; half < 2; half++) {
                int r = r0 + half * 8;
#pragma unroll
                for (int cc = 0; cc < 2; cc++) {
                    float v = acc[im][j8][half * 2 + cc];
                    int c = c0 + cc;
                    if (BIAS) v += bias[bn + c];
                    if (RELU) v = fmaxf(v, 0.0f);
                    uint32_t w;
                    if (MODE == 0) {
                        w = __float_as_uint(v);
                    } else {
                        __nv_bfloat16 h = __float2bfloat16_rn(v);
                        float hf = __bfloat162float(h);
                        __nv_bfloat16 l = __float2bfloat16_rn(v - hf);
                        w = (uint32_t)__bfloat16_as_ushort(h) |
                            ((uint32_t)__bfloat16_as_ushort(l) << 16);
                    }
                    stage[r * EP_LD + c] = w;
                }
            }
        }
    }
    __syncthreads();

    if (MODE == 0) {
        float* Cp = Cf + (long long)z * sC;
#pragma unroll 4
        for (int k2 = 0; k2 < 128; k2++) {
            int idx = tid + k2 * 256;
            int r = idx >> 8, c = idx & 255;
            Cp[(long long)(bm + r) * ldc + bn + c] =
                __uint_as_float(stage[r * EP_LD + c]);
        }
    } else if (MODE == 1) {
        __nv_bfloat16* ChP = Ch + (long long)z * sC;
        __nv_bfloat16* ClP = Cl + (long long)z * sC;
#pragma unroll 4
        for (int k2 = 0; k2 < 64; k2++) {
            int p = tid + k2 * 256;
            int r = p >> 7, cp2 = (p & 127) * 2;
            uint32_t w0 = stage[r * EP_LD + cp2];
            uint32_t w1 = stage[r * EP_LD + cp2 + 1];
            uint32_t hw = (w0 & 0xFFFFu) | (w1 << 16);
            uint32_t lw = (w0 >> 16) | (w1 & 0xFFFF0000u);
            long long o = (long long)(bm + r) * ldc + bn + cp2;
            *(uint32_t*)(ChP + o) = hw;
            *(uint32_t*)(ClP + o) = lw;
        }
    } else {
        // Transposed split store: Vt[b][d][s], b = bm/SEQ, d = bn+c, s = bm%SEQ+r
        long long ob = (long long)(bm >> 11) * ((long long)DIM * SEQ);
        int sbase = bm & (SEQ - 1);
#pragma unroll 1
        for (int cc = 0; cc < 32; cc++) {
            int c = (tid >> 5) + cc * 8;
#pragma unroll
            for (int rr = 0; rr < 4; rr++) {
                int r = (tid & 31) + rr * 32;
                uint32_t w = stage[r * EP_LD + c];
                long long o = ob + (long long)(bn + c) * SEQ + sbase + r;
                Ch[o] = __ushort_as_bfloat16((unsigned short)(w & 0xFFFF));
                Cl[o] = __ushort_as_bfloat16((unsigned short)(w >> 16));
            }
        }
    }
}

// ------------- fp32 -> bf16 hi/lo split (single fused launch) --------------
// Segments (in 1024-element blocks): q,k,v = 8192 blocks each; w = 1024 each.
__global__ __launch_bounds__(256)
void split_all_kernel(const float* __restrict__ q, const float* __restrict__ k,
                      const float* __restrict__ v, const float* __restrict__ wq,
                      const float* __restrict__ wk, const float* __restrict__ wv,
                      __nv_bfloat16* __restrict__ qh, __nv_bfloat16* __restrict__ ql,
                      __nv_bfloat16* __restrict__ kh, __nv_bfloat16* __restrict__ kl,
                      __nv_bfloat16* __restrict__ vh, __nv_bfloat16* __restrict__ vl,
                      __nv_bfloat16* __restrict__ wqh, __nv_bfloat16* __restrict__ wql,
                      __nv_bfloat16* __restrict__ wkh, __nv_bfloat16* __restrict__ wkl,
                      __nv_bfloat16* __restrict__ wvh, __nv_bfloat16* __restrict__ wvl)
{
    int b = blockIdx.x;
    const float* x;
    __nv_bfloat16 *h, *l;
    int off;
    if      (b < 8192)  { x = q;  h = qh;  l = ql;  off = b; }
    else if (b < 16384) { x = k;  h = kh;  l = kl;  off = b - 8192; }
    else if (b < 24576) { x = v;  h = vh;  l = vl;  off = b - 16384; }
    else if (b < 25600) { x = wq; h = wqh; l = wql; off = b - 24576; }
    else if (b < 26624) { x = wk; h = wkh; l = wkl; off = b - 25600; }
    else                { x = wv; h = wvh; l = wvl; off = b - 26624; }

    int i = off * 1024 + threadIdx.x * 4;
    float4 val = *(const float4*)(x + i);
    float vv[4] = {val.x, val.y, val.z, val.w};
    unsigned short hs[4], ls[4];
#pragma unroll
    for (int j = 0; j < 4; j++) {
        __nv_bfloat16 hb = __float2bfloat16_rn(vv[j]);
        float hf = __bfloat162float(hb);
        __nv_bfloat16 lb = __float2bfloat16_rn(vv[j] - hf);
        hs[j] = __bfloat16_as_ushort(hb);
        ls[j] = __bfloat16_as_ushort(lb);
    }
    uint2 hw = make_uint2((uint32_t)hs[0] | ((uint32_t)hs[1] << 16),
                          (uint32_t)hs[2] | ((uint32_t)hs[3] << 16));
    uint2 lw = make_uint2((uint32_t)ls[0] | ((uint32_t)ls[1] << 16),
                          (uint32_t)ls[2] | ((uint32_t)ls[3] << 16));
    *(uint2*)(h + i) = hw;
    *(uint2*)(l + i) = lw;
}

// ---------------------------------------------------------------------------
extern "C" void kernel_launch(void* const* d_in, const int* in_sizes, int n_in,
                              void* d_out, int out_size)
{
    const float* queries = (const float*)d_in[0];
    const float* keys    = (const float*)d_in[1];
    const float* values  = (const float*)d_in[2];
    const float* Wq      = (const float*)d_in[3];
    const float* bq      = (const float*)d_in[4];
    const float* Wk      = (const float*)d_in[5];
    const float* bk      = (const float*)d_in[6];
    const float* Wv      = (const float*)d_in[7];
    const float* bv      = (const float*)d_in[8];
    float* out = (float*)d_out;

    __nv_bfloat16 *qih, *qil, *kih, *kil, *vih, *vil;
    __nv_bfloat16 *wqh, *wql, *wkh, *wkl, *wvh, *wvl;
    __nv_bfloat16 *Qh, *Ql, *Kh, *Kl, *Vth, *Vtl, *Sh, *Sl;
    cudaGetSymbolAddress((void**)&qih, g_qi_h); cudaGetSymbolAddress((void**)&qil, g_qi_l);
    cudaGetSymbolAddress((void**)&kih, g_ki_h); cudaGetSymbolAddress((void**)&kil, g_ki_l);
    cudaGetSymbolAddress((void**)&vih, g_vi_h); cudaGetSymbolAddress((void**)&vil, g_vi_l);
    cudaGetSymbolAddress((void**)&wqh, g_wq_h); cudaGetSymbolAddress((void**)&wql, g_wq_l);
    cudaGetSymbolAddress((void**)&wkh, g_wk_h); cudaGetSymbolAddress((void**)&wkl, g_wk_l);
    cudaGetSymbolAddress((void**)&wvh, g_wv_h); cudaGetSymbolAddress((void**)&wvl, g_wv_l);
    cudaGetSymbolAddress((void**)&Qh,  g_Q_h);  cudaGetSymbolAddress((void**)&Ql,  g_Q_l);
    cudaGetSymbolAddress((void**)&Kh,  g_K_h);  cudaGetSymbolAddress((void**)&Kl,  g_K_l);
    cudaGetSymbolAddress((void**)&Vth, g_Vt_h); cudaGetSymbolAddress((void**)&Vtl, g_Vt_l);
    cudaGetSymbolAddress((void**)&Sh,  g_S_h);  cudaGetSymbolAddress((void**)&Sl,  g_S_l);

    cudaFuncSetAttribute(tc_gemm<1, false, true>,
                         cudaFuncAttributeMaxDynamicSharedMemorySize, SMEM_TOTAL);
    cudaFuncSetAttribute(tc_gemm<2, false, true>,
                         cudaFuncAttributeMaxDynamicSharedMemorySize, SMEM_TOTAL);
    cudaFuncSetAttribute(tc_gemm<1, true, false>,
                         cudaFuncAttributeMaxDynamicSharedMemorySize, SMEM_TOTAL);
    cudaFuncSetAttribute(tc_gemm<0, false, false>,
                         cudaFuncAttributeMaxDynamicSharedMemorySize, SMEM_TOTAL);

    // 0) split inputs + weights into bf16 hi/lo (one fused launch)
    split_all_kernel<<<27648, 256>>>(queries, keys, values, Wq, Wk, Wv,
                                     qih, qil, kih, kil, vih, vil,
                                     wqh, wql, wkh, wkl, wvh, wvl);

    const int Mproj = BATCH * SEQ;       // 8192
    dim3 blk(256);

    // 1) projections (M=8192, N=1024, K=1024)
    dim3 gp(DIM / BN, Mproj / BM, 1);
    tc_gemm<1, false, true><<<gp, blk, SMEM_TOTAL>>>(
        qih, qil, wqh, wql, bq, nullptr, Qh, Ql, DIM, DIM, 0, 0, 0);
    tc_gemm<1, false, true><<<gp, blk, SMEM_TOTAL>>>(
        kih, kil, wkh, wkl, bk, nullptr, Kh, Kl, DIM, DIM, 0, 0, 0);
    tc_gemm<2, false, true><<<gp, blk, SMEM_TOTAL>>>(
        vih, vil, wvh, wvl, bv, nullptr, Vth, Vtl, DIM, 0, 0, 0, 0);

    // 2) scores: relu(Q @ K^T) per batch (M=2048, N=2048, K=1024)
    dim3 gs(SEQ / BN, SEQ / BM, BATCH);
    tc_gemm<1, true, false><<<gs, blk, SMEM_TOTAL>>>(
        Qh, Ql, Kh, Kl, nullptr, nullptr, Sh, Sl, DIM, SEQ,
        (long long)SEQ * DIM, (long long)SEQ * DIM, (long long)SEQ * SEQ);

    // 3) output: Sc @ Vt^T per batch (M=2048, N=1024, K=2048)
    dim3 go(DIM / BN, SEQ / BM, BATCH);
    tc_gemm<0, false, false><<<go, blk, SMEM_TOTAL>>>(
        Sh, Sl, Vth, Vtl, nullptr, out, nullptr, nullptr, SEQ, DIM,
        (long long)SEQ * SEQ, (long long)DIM * SEQ, (long long)SEQ * DIM);

    (void)in_sizes; (void)n_in; (void)out_size;
}